// round 1
// baseline (speedup 1.0000x reference)
#include <cuda_runtime.h>
#include <math.h>
#include <stdint.h>

// ---------------- problem constants ----------------
#define NN      65536      // nodes
#define EE      1048576    // edges
#define BB      256        // graphs
#define LIN_INX 16384
#define LIN_OUTX 6400
#define EPSBN   1e-5f

// ---------------- scratch (device globals; allocation-free) ----------------
__device__ __align__(16) float g_P  [NN * 128];   // x @ Wl^T  (scatter source)
__device__ __align__(16) float g_pre[NN * 128];   // x @ Wr^T + b, then += agg*inv
__device__ __align__(16) float g_agg[NN * 128];   // scatter destination
__device__ __align__(16) float g_bufA[NN * 128];  // layer outputs (ping)
__device__ __align__(16) float g_bufB[NN * 128];  // layer outputs (pong)
__device__ __align__(16) float g_Y1 [BB * LIN_OUTX];
__device__ __align__(16) float g_mu [BB * LIN_OUTX];
__device__ __align__(16) float g_sg [BB * LIN_OUTX];
__device__ float g_inv[NN];
__device__ int   g_cnt[NN];
__device__ float g_stats[256];   // [0:128) sum, [128:256) sumsq
__device__ float g_scale[128];
__device__ float g_shift[128];

// ---------------- small kernels ----------------
__global__ void count_edges(const int* __restrict__ dst) {
    int e = blockIdx.x * blockDim.x + threadIdx.x;
    if (e < EE) atomicAdd(&g_cnt[__ldg(dst + e)], 1);
}

__global__ void calc_inv() {
    int i = blockIdx.x * blockDim.x + threadIdx.x;
    if (i < NN) g_inv[i] = 1.0f / fmaxf((float)g_cnt[i], 1.0f);
}

// scatter: agg[dst] += P[src], vector f32x4 reductions (sm_90+)
template<int H>
__global__ void scatter_add(const int* __restrict__ src, const int* __restrict__ dst,
                            const float* __restrict__ P) {
    const int H4 = H / 4;
    unsigned idx = blockIdx.x * blockDim.x + threadIdx.x;   // total = EE*H4 (exact)
    int e = idx / H4;
    int s = idx - e * H4;
    int sn = __ldg(src + e);
    int dn = __ldg(dst + e);
    float4 v = *(const float4*)(P + (size_t)sn * H + s * 4);
    float* a = g_agg + (size_t)dn * H + s * 4;
    asm volatile("red.global.add.v4.f32 [%0], {%1,%2,%3,%4};"
                 :: "l"(a), "f"(v.x), "f"(v.y), "f"(v.z), "f"(v.w) : "memory");
}

// pre += agg*inv (in place) and accumulate per-column sum/sumsq
template<int H>
__global__ void __launch_bounds__(256) combine_stats(float* __restrict__ pre) {
    const int G = 256 / H;
    const int ROWS = 128;
    int tid = threadIdx.x;
    int col = tid % H;
    int rg  = tid / H;
    size_t base = (size_t)blockIdx.x * ROWS;
    float s = 0.f, s2 = 0.f;
    for (int r = rg; r < ROWS; r += G) {
        size_t i = base + r;
        float v = pre[i * H + col] + g_agg[i * H + col] * g_inv[i];
        pre[i * H + col] = v;
        s += v; s2 += v * v;
    }
    __shared__ float sh[256], sh2[256];
    sh[tid] = s; sh2[tid] = s2;
    __syncthreads();
    if (rg == 0) {
#pragma unroll
        for (int g = 1; g < G; g++) { s += sh[g * H + col]; s2 += sh2[g * H + col]; }
        atomicAdd(&g_stats[col], s);
        atomicAdd(&g_stats[128 + col], s2);
    }
}

template<int H>
__global__ void finalize_stats(const float* __restrict__ gamma, const float* __restrict__ beta) {
    int c = threadIdx.x;
    if (c < H) {
        float m   = g_stats[c] * (1.0f / NN);
        float var = g_stats[128 + c] * (1.0f / NN) - m * m;
        float sc  = gamma[c] * rsqrtf(var + EPSBN);
        g_scale[c] = sc;
        g_shift[c] = beta[c] - m * sc;
    }
}

template<int H>
__global__ void bn_relu_kernel(const float* __restrict__ pre, float* __restrict__ out) {
    unsigned idx = blockIdx.x * blockDim.x + threadIdx.x;   // total = NN*H/4 (exact)
    float4 v = *(const float4*)(pre + (size_t)idx * 4);
    int c = (idx * 4) & (H - 1);
    v.x = fmaxf(fmaf(v.x, g_scale[c + 0], g_shift[c + 0]), 0.f);
    v.y = fmaxf(fmaf(v.y, g_scale[c + 1], g_shift[c + 1]), 0.f);
    v.z = fmaxf(fmaf(v.z, g_scale[c + 2], g_shift[c + 2]), 0.f);
    v.w = fmaxf(fmaf(v.w, g_scale[c + 3], g_shift[c + 3]), 0.f);
    *(float4*)(out + (size_t)idx * 4) = v;
}

// final head batchnorm over 256 rows, one thread per column
__global__ void head_bn(const float* __restrict__ P, const float* __restrict__ gamma,
                        const float* __restrict__ beta, float* __restrict__ out) {
    int c = blockIdx.x * blockDim.x + threadIdx.x;
    if (c >= LIN_OUTX) return;
    float s = 0.f, s2 = 0.f;
    for (int r = 0; r < BB; r++) {
        float v = P[(size_t)r * LIN_OUTX + c];
        s += v; s2 += v * v;
    }
    float m   = s * (1.0f / BB);
    float var = s2 * (1.0f / BB) - m * m;
    float sc  = gamma[c] * rsqrtf(var + EPSBN);
    float shf = beta[c] - m * sc;
    for (int r = 0; r < BB; r++)
        out[(size_t)r * LIN_OUTX + c] = P[(size_t)r * LIN_OUTX + c] * sc + shf;
}

// ---------------- SGEMM: C[M,N] = act(A[M,K] @ W[N,K]^T + bias) ----------------
// BM=128, BN=64, BK=16, 256 threads, 8x4 register tile, prefetched global loads.
// ACT: 0 none, 2 tanh
template<int ACT>
__global__ void __launch_bounds__(256) sgemm_nt(
    const float* __restrict__ A, const float* __restrict__ W,
    const float* __restrict__ bias, float* __restrict__ C,
    int M, int N, int K)
{
    __shared__ float As[16][132];
    __shared__ float Ws[16][68];
    const int tid = threadIdx.x;
    const int m0 = blockIdx.y * 128;
    const int n0 = blockIdx.x * 64;
    const int tx = tid & 15;
    const int ty = tid >> 4;
    const int lr = tid >> 2;       // 0..63
    const int lq = (tid & 3) * 4;  // 0,4,8,12

    const float* Ag0 = A + (size_t)(m0 + lr) * K + lq;
    const float* Ag1 = A + (size_t)(m0 + 64 + lr) * K + lq;
    const float* Wg  = W + (size_t)(n0 + lr) * K + lq;

    float acc[8][4];
#pragma unroll
    for (int i = 0; i < 8; i++)
#pragma unroll
        for (int j = 0; j < 4; j++) acc[i][j] = 0.f;

    float4 a0 = *(const float4*)(Ag0);
    float4 a1 = *(const float4*)(Ag1);
    float4 w0 = *(const float4*)(Wg);

    for (int kt = 0; kt < K; kt += 16) {
        __syncthreads();
        As[lq + 0][lr]      = a0.x; As[lq + 1][lr]      = a0.y;
        As[lq + 2][lr]      = a0.z; As[lq + 3][lr]      = a0.w;
        As[lq + 0][lr + 64] = a1.x; As[lq + 1][lr + 64] = a1.y;
        As[lq + 2][lr + 64] = a1.z; As[lq + 3][lr + 64] = a1.w;
        Ws[lq + 0][lr] = w0.x; Ws[lq + 1][lr] = w0.y;
        Ws[lq + 2][lr] = w0.z; Ws[lq + 3][lr] = w0.w;
        __syncthreads();

        int kn = kt + 16;
        if (kn < K) {   // prefetch next tile; latency hidden under FFMAs below
            a0 = *(const float4*)(Ag0 + kn);
            a1 = *(const float4*)(Ag1 + kn);
            w0 = *(const float4*)(Wg  + kn);
        }

#pragma unroll
        for (int k = 0; k < 16; k++) {
            float4 aa0 = *(const float4*)&As[k][ty * 8];
            float4 aa1 = *(const float4*)&As[k][ty * 8 + 4];
            float4 bb  = *(const float4*)&Ws[k][tx * 4];
            float a[8] = {aa0.x, aa0.y, aa0.z, aa0.w, aa1.x, aa1.y, aa1.z, aa1.w};
            float b[4] = {bb.x, bb.y, bb.z, bb.w};
#pragma unroll
            for (int i = 0; i < 8; i++)
#pragma unroll
                for (int j = 0; j < 4; j++)
                    acc[i][j] = fmaf(a[i], b[j], acc[i][j]);
        }
    }

    float4 bv = make_float4(0.f, 0.f, 0.f, 0.f);
    if (bias) bv = *(const float4*)(bias + n0 + tx * 4);
#pragma unroll
    for (int i = 0; i < 8; i++) {
        float4 o;
        o.x = acc[i][0] + bv.x; o.y = acc[i][1] + bv.y;
        o.z = acc[i][2] + bv.z; o.w = acc[i][3] + bv.w;
        if (ACT == 2) { o.x = tanhf(o.x); o.y = tanhf(o.y); o.z = tanhf(o.z); o.w = tanhf(o.w); }
        *(float4*)(C + (size_t)(m0 + ty * 8 + i) * N + n0 + tx * 4) = o;
    }
}

// ---------------- host orchestration ----------------
static void* symaddr(const void* sym) {
    void* p = nullptr;
    cudaGetSymbolAddress(&p, sym);
    return p;
}

extern "C" void kernel_launch(void* const* d_in, const int* in_sizes, int n_in,
                              void* d_out, int out_size)
{
    const float* x    = (const float*)d_in[0];
    const int*   ei   = (const int*)  d_in[1];
    const int*   srcI = ei;
    const int*   dstI = ei + EE;
    const float *W1l = (const float*)d_in[3],  *b1l = (const float*)d_in[4],  *W1r = (const float*)d_in[5];
    const float *gm1 = (const float*)d_in[6],  *be1 = (const float*)d_in[7];
    const float *W2l = (const float*)d_in[8],  *b2l = (const float*)d_in[9],  *W2r = (const float*)d_in[10];
    const float *gm2 = (const float*)d_in[11], *be2 = (const float*)d_in[12];
    const float *W3l = (const float*)d_in[13], *b3l = (const float*)d_in[14], *W3r = (const float*)d_in[15];
    const float *gm3 = (const float*)d_in[16], *be3 = (const float*)d_in[17];
    const float *Wlin = (const float*)d_in[18], *blin = (const float*)d_in[19];
    const float *Wmu  = (const float*)d_in[20], *bmu  = (const float*)d_in[21];
    const float *Wsig = (const float*)d_in[22], *bsig = (const float*)d_in[23];
    const float *gfx  = (const float*)d_in[24], *bfx  = (const float*)d_in[25];
    const float *gfs  = (const float*)d_in[26], *bfs  = (const float*)d_in[27];
    float* out = (float*)d_out;

    float* pP    = (float*)symaddr(g_P);
    float* pPre  = (float*)symaddr(g_pre);
    float* pAgg  = (float*)symaddr(g_agg);
    float* pA    = (float*)symaddr(g_bufA);
    float* pB    = (float*)symaddr(g_bufB);
    float* pY1   = (float*)symaddr(g_Y1);
    float* pMu   = (float*)symaddr(g_mu);
    float* pSg   = (float*)symaddr(g_sg);
    int*   pCnt  = (int*)  symaddr(g_cnt);
    float* pStat = (float*)symaddr(g_stats);

    // degree counts (once per call; graph is the same for all three layers)
    cudaMemsetAsync(pCnt, 0, NN * sizeof(int));
    count_edges<<<EE / 256, 256>>>(dstI);
    calc_inv<<<NN / 256, 256>>>();

    // ---- layer 1: in x [N,128] -> out bufA [N,128] ----
    {
        dim3 gl(128 / 64, NN / 128);
        sgemm_nt<0><<<gl, 256>>>(x, W1l, nullptr, pP,   NN, 128, 128);
        sgemm_nt<0><<<gl, 256>>>(x, W1r, b1l,     pPre, NN, 128, 128);
        cudaMemsetAsync(pAgg, 0, (size_t)NN * 128 * sizeof(float));
        scatter_add<128><<<EE * 32 / 256, 256>>>(srcI, dstI, pP);
        cudaMemsetAsync(pStat, 0, 256 * sizeof(float));
        combine_stats<128><<<NN / 128, 256>>>(pPre);
        finalize_stats<128><<<1, 128>>>(gm1, be1);
        bn_relu_kernel<128><<<NN * 128 / 4 / 256, 256>>>(pPre, pA);
    }
    // ---- layer 2: bufA -> bufB [N,128] ----
    {
        dim3 gl(128 / 64, NN / 128);
        sgemm_nt<0><<<gl, 256>>>(pA, W2l, nullptr, pP,   NN, 128, 128);
        sgemm_nt<0><<<gl, 256>>>(pA, W2r, b2l,     pPre, NN, 128, 128);
        cudaMemsetAsync(pAgg, 0, (size_t)NN * 128 * sizeof(float));
        scatter_add<128><<<EE * 32 / 256, 256>>>(srcI, dstI, pP);
        cudaMemsetAsync(pStat, 0, 256 * sizeof(float));
        combine_stats<128><<<NN / 128, 256>>>(pPre);
        finalize_stats<128><<<1, 128>>>(gm2, be2);
        bn_relu_kernel<128><<<NN * 128 / 4 / 256, 256>>>(pPre, pB);
    }
    // ---- layer 3: bufB [N,128] -> bufA [N,64] ----
    {
        dim3 gl(64 / 64, NN / 128);
        sgemm_nt<0><<<gl, 256>>>(pB, W3l, nullptr, pP,   NN, 64, 128);
        sgemm_nt<0><<<gl, 256>>>(pB, W3r, b3l,     pPre, NN, 64, 128);
        cudaMemsetAsync(pAgg, 0, (size_t)NN * 64 * sizeof(float));
        scatter_add<64><<<EE * 16 / 256, 256>>>(srcI, dstI, pP);
        cudaMemsetAsync(pStat, 0, 256 * sizeof(float));
        combine_stats<64><<<NN / 128, 256>>>(pPre);
        finalize_stats<64><<<1, 64>>>(gm3, be3);
        bn_relu_kernel<64><<<NN * 64 / 4 / 256, 256>>>(pPre, pA);
    }

    // ---- head: bufA viewed as [256, 16384] ----
    {
        dim3 gh(LIN_OUTX / 64, BB / 128);   // (100, 2)
        sgemm_nt<2><<<gh, 256>>>(pA,  Wlin, blin, pY1, BB, LIN_OUTX, LIN_INX);
        sgemm_nt<0><<<gh, 256>>>(pY1, Wmu,  bmu,  pMu, BB, LIN_OUTX, LIN_OUTX);
        sgemm_nt<0><<<gh, 256>>>(pY1, Wsig, bsig, pSg, BB, LIN_OUTX, LIN_OUTX);
        head_bn<<<(LIN_OUTX + 255) / 256, 256>>>(pMu, gfx, bfx, out);
        head_bn<<<(LIN_OUTX + 255) / 256, 256>>>(pSg, gfs, bfs, out + (size_t)BB * LIN_OUTX);
    }
}

// round 2
// speedup vs baseline: 1.1570x; 1.1570x over previous
#include <cuda_runtime.h>
#include <math.h>
#include <stdint.h>

// ---------------- problem constants ----------------
#define NN      65536      // nodes
#define EE      1048576    // edges
#define BB      256        // graphs
#define LIN_INX 16384
#define LIN_OUTX 6400
#define EPSBN   1e-5f

// ---------------- scratch (device globals; allocation-free) ----------------
__device__ __align__(16) float g_P  [NN * 128];   // x @ Wl^T  (scatter source)
__device__ __align__(16) float g_pre[NN * 128];   // x @ Wr^T + b, then += agg*inv
__device__ __align__(16) float g_agg[NN * 128];   // scatter destination
__device__ __align__(16) float g_bufA[NN * 128];  // layer outputs (ping)
__device__ __align__(16) float g_bufB[NN * 128];  // layer outputs (pong)
__device__ __align__(16) float g_Y1 [BB * LIN_OUTX];
__device__ __align__(16) float g_mu [BB * LIN_OUTX];
__device__ __align__(16) float g_sg [BB * LIN_OUTX];
__device__ float g_inv[NN];
__device__ int   g_cnt[NN];
__device__ float g_stats[256];   // [0:128) sum, [128:256) sumsq
__device__ float g_scale[128];
__device__ float g_shift[128];

// ---------------- small kernels ----------------
__global__ void count_edges(const int* __restrict__ dst) {
    int e = blockIdx.x * blockDim.x + threadIdx.x;
    if (e < EE) atomicAdd(&g_cnt[__ldg(dst + e)], 1);
}

__global__ void calc_inv() {
    int i = blockIdx.x * blockDim.x + threadIdx.x;
    if (i < NN) g_inv[i] = 1.0f / fmaxf((float)g_cnt[i], 1.0f);
}

// scatter: agg[dst] += P[src], vector f32x4 reductions (sm_90+)
template<int H>
__global__ void scatter_add(const int* __restrict__ src, const int* __restrict__ dst,
                            const float* __restrict__ P) {
    const int H4 = H / 4;
    unsigned idx = blockIdx.x * blockDim.x + threadIdx.x;   // total = EE*H4 (exact)
    int e = idx / H4;
    int s = idx - e * H4;
    int sn = __ldg(src + e);
    int dn = __ldg(dst + e);
    float4 v = *(const float4*)(P + (size_t)sn * H + s * 4);
    float* a = g_agg + (size_t)dn * H + s * 4;
    asm volatile("red.global.add.v4.f32 [%0], {%1,%2,%3,%4};"
                 :: "l"(a), "f"(v.x), "f"(v.y), "f"(v.z), "f"(v.w) : "memory");
}

// pre += agg*inv (in place) and accumulate per-column sum/sumsq
template<int H>
__global__ void __launch_bounds__(256) combine_stats(float* __restrict__ pre) {
    const int G = 256 / H;
    const int ROWS = 128;
    int tid = threadIdx.x;
    int col = tid % H;
    int rg  = tid / H;
    size_t base = (size_t)blockIdx.x * ROWS;
    float s = 0.f, s2 = 0.f;
    for (int r = rg; r < ROWS; r += G) {
        size_t i = base + r;
        float v = pre[i * H + col] + g_agg[i * H + col] * g_inv[i];
        pre[i * H + col] = v;
        s += v; s2 += v * v;
    }
    __shared__ float sh[256], sh2[256];
    sh[tid] = s; sh2[tid] = s2;
    __syncthreads();
    if (rg == 0) {
#pragma unroll
        for (int g = 1; g < G; g++) { s += sh[g * H + col]; s2 += sh2[g * H + col]; }
        atomicAdd(&g_stats[col], s);
        atomicAdd(&g_stats[128 + col], s2);
    }
}

template<int H>
__global__ void finalize_stats(const float* __restrict__ gamma, const float* __restrict__ beta) {
    int c = threadIdx.x;
    if (c < H) {
        float m   = g_stats[c] * (1.0f / NN);
        float var = g_stats[128 + c] * (1.0f / NN) - m * m;
        float sc  = gamma[c] * rsqrtf(var + EPSBN);
        g_scale[c] = sc;
        g_shift[c] = beta[c] - m * sc;
    }
}

template<int H>
__global__ void bn_relu_kernel(const float* __restrict__ pre, float* __restrict__ out) {
    unsigned idx = blockIdx.x * blockDim.x + threadIdx.x;   // total = NN*H/4 (exact)
    float4 v = *(const float4*)(pre + (size_t)idx * 4);
    int c = (idx * 4) & (H - 1);
    v.x = fmaxf(fmaf(v.x, g_scale[c + 0], g_shift[c + 0]), 0.f);
    v.y = fmaxf(fmaf(v.y, g_scale[c + 1], g_shift[c + 1]), 0.f);
    v.z = fmaxf(fmaf(v.z, g_scale[c + 2], g_shift[c + 2]), 0.f);
    v.w = fmaxf(fmaf(v.w, g_scale[c + 3], g_shift[c + 3]), 0.f);
    *(float4*)(out + (size_t)idx * 4) = v;
}

// final head batchnorm over 256 rows, one thread per column
__global__ void head_bn(const float* __restrict__ P, const float* __restrict__ gamma,
                        const float* __restrict__ beta, float* __restrict__ out) {
    int c = blockIdx.x * blockDim.x + threadIdx.x;
    if (c >= LIN_OUTX) return;
    float s = 0.f, s2 = 0.f;
    for (int r = 0; r < BB; r++) {
        float v = P[(size_t)r * LIN_OUTX + c];
        s += v; s2 += v * v;
    }
    float m   = s * (1.0f / BB);
    float var = s2 * (1.0f / BB) - m * m;
    float sc  = gamma[c] * rsqrtf(var + EPSBN);
    float shf = beta[c] - m * sc;
    for (int r = 0; r < BB; r++)
        out[(size_t)r * LIN_OUTX + c] = P[(size_t)r * LIN_OUTX + c] * sc + shf;
}

// ---------------- fp32 SGEMM (layer GEMMs, K=128): unchanged ----------------
template<int ACT>
__global__ void __launch_bounds__(256) sgemm_nt(
    const float* __restrict__ A, const float* __restrict__ W,
    const float* __restrict__ bias, float* __restrict__ C,
    int M, int N, int K)
{
    __shared__ float As[16][132];
    __shared__ float Ws[16][68];
    const int tid = threadIdx.x;
    const int m0 = blockIdx.y * 128;
    const int n0 = blockIdx.x * 64;
    const int tx = tid & 15;
    const int ty = tid >> 4;
    const int lr = tid >> 2;       // 0..63
    const int lq = (tid & 3) * 4;  // 0,4,8,12

    const float* Ag0 = A + (size_t)(m0 + lr) * K + lq;
    const float* Ag1 = A + (size_t)(m0 + 64 + lr) * K + lq;
    const float* Wg  = W + (size_t)(n0 + lr) * K + lq;

    float acc[8][4];
#pragma unroll
    for (int i = 0; i < 8; i++)
#pragma unroll
        for (int j = 0; j < 4; j++) acc[i][j] = 0.f;

    float4 a0 = *(const float4*)(Ag0);
    float4 a1 = *(const float4*)(Ag1);
    float4 w0 = *(const float4*)(Wg);

    for (int kt = 0; kt < K; kt += 16) {
        __syncthreads();
        As[lq + 0][lr]      = a0.x; As[lq + 1][lr]      = a0.y;
        As[lq + 2][lr]      = a0.z; As[lq + 3][lr]      = a0.w;
        As[lq + 0][lr + 64] = a1.x; As[lq + 1][lr + 64] = a1.y;
        As[lq + 2][lr + 64] = a1.z; As[lq + 3][lr + 64] = a1.w;
        Ws[lq + 0][lr] = w0.x; Ws[lq + 1][lr] = w0.y;
        Ws[lq + 2][lr] = w0.z; Ws[lq + 3][lr] = w0.w;
        __syncthreads();

        int kn = kt + 16;
        if (kn < K) {
            a0 = *(const float4*)(Ag0 + kn);
            a1 = *(const float4*)(Ag1 + kn);
            w0 = *(const float4*)(Wg  + kn);
        }

#pragma unroll
        for (int k = 0; k < 16; k++) {
            float4 aa0 = *(const float4*)&As[k][ty * 8];
            float4 aa1 = *(const float4*)&As[k][ty * 8 + 4];
            float4 bb  = *(const float4*)&Ws[k][tx * 4];
            float a[8] = {aa0.x, aa0.y, aa0.z, aa0.w, aa1.x, aa1.y, aa1.z, aa1.w};
            float b[4] = {bb.x, bb.y, bb.z, bb.w};
#pragma unroll
            for (int i = 0; i < 8; i++)
#pragma unroll
                for (int j = 0; j < 4; j++)
                    acc[i][j] = fmaf(a[i], b[j], acc[i][j]);
        }
    }

    float4 bv = make_float4(0.f, 0.f, 0.f, 0.f);
    if (bias) bv = *(const float4*)(bias + n0 + tx * 4);
#pragma unroll
    for (int i = 0; i < 8; i++) {
        float4 o;
        o.x = acc[i][0] + bv.x; o.y = acc[i][1] + bv.y;
        o.z = acc[i][2] + bv.z; o.w = acc[i][3] + bv.w;
        if (ACT == 2) { o.x = tanhf(o.x); o.y = tanhf(o.y); o.z = tanhf(o.z); o.w = tanhf(o.w); }
        *(float4*)(C + (size_t)(m0 + ty * 8 + i) * N + n0 + tx * 4) = o;
    }
}

// ---------------- tf32 tensor-core GEMM (head GEMMs) ----------------
// C[256, N] = act(A[256, K] @ W[N, K]^T + bias)
// BM=256 (whole M), BN=64, BK=16. 8 warps: 4 along M (64 rows) x 2 along N (32 cols).
// Double-buffered dynamic smem, tf32 converted at smem store (cvt.rna).

__device__ __forceinline__ uint32_t f2tf32(float x) {
    uint32_t r;
    asm("cvt.rna.tf32.f32 %0, %1;" : "=r"(r) : "f"(x));
    return r;
}

__device__ __forceinline__ void mma_tf32(float c[4], const uint32_t a[4], const uint32_t b[2]) {
    asm("mma.sync.aligned.m16n8k8.row.col.f32.tf32.tf32.f32 "
        "{%0,%1,%2,%3},{%4,%5,%6,%7},{%8,%9},{%0,%1,%2,%3};"
        : "+f"(c[0]), "+f"(c[1]), "+f"(c[2]), "+f"(c[3])
        : "r"(a[0]), "r"(a[1]), "r"(a[2]), "r"(a[3]), "r"(b[0]), "r"(b[1]));
}

#define TPITCH 20                      // BK(16) + 4 pad, in uint32
#define ABUF   (256 * TPITCH)          // 5120
#define WBASE  (2 * ABUF)              // 10240
#define WBUF   (64 * TPITCH)           // 1280
#define TF32_SMEM_BYTES ((WBASE + 2 * WBUF) * 4)   // 51200

__device__ __forceinline__ void gemm_tf32_core(
    const float* __restrict__ A, const float* __restrict__ W,
    const float* __restrict__ bias, float* __restrict__ C,
    int N, int K, int n0, int act, uint32_t* sh)
{
    const int tid  = threadIdx.x;
    const int lane = tid & 31;
    const int wid  = tid >> 5;
    const int mw   = wid & 3;          // 0..3  -> 64 M-rows each
    const int nw   = wid >> 2;         // 0..1  -> 32 N-cols each
    const int gid  = lane >> 2;        // 0..7
    const int tig  = lane & 3;         // 0..3

    const int arow = tid >> 2;         // 0..63 (A load, +64*t)
    const int ac4  = tid & 3;          // float4 index within K-chunk of 16

    const float* Ag = A + (size_t)arow * K + ac4 * 4;
    const float* Wg = W + (size_t)(n0 + arow) * K + ac4 * 4;

    float acc[4][4][4];
#pragma unroll
    for (int i = 0; i < 4; i++)
#pragma unroll
        for (int j = 0; j < 4; j++)
#pragma unroll
            for (int q = 0; q < 4; q++) acc[i][j][q] = 0.f;

    float4 av[4], wv;

    // prologue: load tile 0
#pragma unroll
    for (int t = 0; t < 4; t++) av[t] = *(const float4*)(Ag + (size_t)(64 * t) * K);
    wv = *(const float4*)(Wg);

    auto store_tile = [&](int buf) {
        uint32_t* ap = sh + buf * ABUF;
        uint32_t* wp = sh + WBASE + buf * WBUF;
#pragma unroll
        for (int t = 0; t < 4; t++) {
            uint32_t* d = ap + (arow + 64 * t) * TPITCH + ac4 * 4;
            d[0] = f2tf32(av[t].x); d[1] = f2tf32(av[t].y);
            d[2] = f2tf32(av[t].z); d[3] = f2tf32(av[t].w);
        }
        uint32_t* d = wp + arow * TPITCH + ac4 * 4;
        d[0] = f2tf32(wv.x); d[1] = f2tf32(wv.y);
        d[2] = f2tf32(wv.z); d[3] = f2tf32(wv.w);
    };

    store_tile(0);
    __syncthreads();

    const int ntiles = K / 16;
    for (int it = 0; it < ntiles; it++) {
        int buf = it & 1;
        // prefetch next tile into regs
        if (it + 1 < ntiles) {
            int kn = (it + 1) * 16;
#pragma unroll
            for (int t = 0; t < 4; t++) av[t] = *(const float4*)(Ag + (size_t)(64 * t) * K + kn);
            wv = *(const float4*)(Wg + kn);
        }

        const uint32_t* ap = sh + buf * ABUF;
        const uint32_t* wp = sh + WBASE + buf * WBUF;

#pragma unroll
        for (int s = 0; s < 2; s++) {          // two k8 steps per tile
            const int k0 = s * 8;
            uint32_t afr[4][4], bfr[4][2];
#pragma unroll
            for (int i = 0; i < 4; i++) {
                int r = mw * 64 + i * 16 + gid;
                afr[i][0] = ap[(r    ) * TPITCH + k0 + tig];
                afr[i][1] = ap[(r + 8) * TPITCH + k0 + tig];
                afr[i][2] = ap[(r    ) * TPITCH + k0 + tig + 4];
                afr[i][3] = ap[(r + 8) * TPITCH + k0 + tig + 4];
            }
#pragma unroll
            for (int j = 0; j < 4; j++) {
                int r = nw * 32 + j * 8 + gid;
                bfr[j][0] = wp[r * TPITCH + k0 + tig];
                bfr[j][1] = wp[r * TPITCH + k0 + tig + 4];
            }
#pragma unroll
            for (int i = 0; i < 4; i++)
#pragma unroll
                for (int j = 0; j < 4; j++)
                    mma_tf32(acc[i][j], afr[i], bfr[j]);
        }

        if (it + 1 < ntiles) store_tile(buf ^ 1);
        __syncthreads();
    }

    // epilogue
#pragma unroll
    for (int i = 0; i < 4; i++) {
        int mrow = mw * 64 + i * 16 + gid;
#pragma unroll
        for (int j = 0; j < 4; j++) {
            int ncol = n0 + nw * 32 + j * 8 + 2 * tig;
            float bx = bias ? bias[ncol] : 0.f;
            float by = bias ? bias[ncol + 1] : 0.f;
            float o0 = acc[i][j][0] + bx, o1 = acc[i][j][1] + by;
            float o2 = acc[i][j][2] + bx, o3 = acc[i][j][3] + by;
            if (act == 2) { o0 = tanhf(o0); o1 = tanhf(o1); o2 = tanhf(o2); o3 = tanhf(o3); }
            *(float2*)(C + (size_t)mrow * N + ncol)       = make_float2(o0, o1);
            *(float2*)(C + (size_t)(mrow + 8) * N + ncol) = make_float2(o2, o3);
        }
    }
}

template<int ACT>
__global__ void __launch_bounds__(256, 1) gemm_tf32(
    const float* __restrict__ A, const float* __restrict__ W,
    const float* __restrict__ bias, float* __restrict__ C, int N, int K)
{
    extern __shared__ uint32_t sh[];
    gemm_tf32_core(A, W, bias, C, N, K, blockIdx.x * 64, ACT, sh);
}

// fused mu+sigma: same A, two weight sets; grid.x = 2 * (N/64)
__global__ void __launch_bounds__(256, 1) gemm_tf32_dual(
    const float* __restrict__ A,
    const float* __restrict__ W0, const float* __restrict__ b0, float* __restrict__ C0,
    const float* __restrict__ W1, const float* __restrict__ b1, float* __restrict__ C1,
    int N, int K)
{
    extern __shared__ uint32_t sh[];
    int nblk = N / 64;
    int bx = blockIdx.x;
    if (bx < nblk)
        gemm_tf32_core(A, W0, b0, C0, N, K, bx * 64, 0, sh);
    else
        gemm_tf32_core(A, W1, b1, C1, N, K, (bx - nblk) * 64, 0, sh);
}

// ---------------- host orchestration ----------------
static void* symaddr(const void* sym) {
    void* p = nullptr;
    cudaGetSymbolAddress(&p, sym);
    return p;
}

extern "C" void kernel_launch(void* const* d_in, const int* in_sizes, int n_in,
                              void* d_out, int out_size)
{
    const float* x    = (const float*)d_in[0];
    const int*   ei   = (const int*)  d_in[1];
    const int*   srcI = ei;
    const int*   dstI = ei + EE;
    const float *W1l = (const float*)d_in[3],  *b1l = (const float*)d_in[4],  *W1r = (const float*)d_in[5];
    const float *gm1 = (const float*)d_in[6],  *be1 = (const float*)d_in[7];
    const float *W2l = (const float*)d_in[8],  *b2l = (const float*)d_in[9],  *W2r = (const float*)d_in[10];
    const float *gm2 = (const float*)d_in[11], *be2 = (const float*)d_in[12];
    const float *W3l = (const float*)d_in[13], *b3l = (const float*)d_in[14], *W3r = (const float*)d_in[15];
    const float *gm3 = (const float*)d_in[16], *be3 = (const float*)d_in[17];
    const float *Wlin = (const float*)d_in[18], *blin = (const float*)d_in[19];
    const float *Wmu  = (const float*)d_in[20], *bmu  = (const float*)d_in[21];
    const float *Wsig = (const float*)d_in[22], *bsig = (const float*)d_in[23];
    const float *gfx  = (const float*)d_in[24], *bfx  = (const float*)d_in[25];
    const float *gfs  = (const float*)d_in[26], *bfs  = (const float*)d_in[27];
    float* out = (float*)d_out;

    float* pP    = (float*)symaddr(g_P);
    float* pPre  = (float*)symaddr(g_pre);
    float* pAgg  = (float*)symaddr(g_agg);
    float* pA    = (float*)symaddr(g_bufA);
    float* pB    = (float*)symaddr(g_bufB);
    float* pY1   = (float*)symaddr(g_Y1);
    float* pMu   = (float*)symaddr(g_mu);
    float* pSg   = (float*)symaddr(g_sg);
    int*   pCnt  = (int*)  symaddr(g_cnt);
    float* pStat = (float*)symaddr(g_stats);

    static bool attr_done = false;
    if (!attr_done) {
        cudaFuncSetAttribute(gemm_tf32<0>,  cudaFuncAttributeMaxDynamicSharedMemorySize, TF32_SMEM_BYTES);
        cudaFuncSetAttribute(gemm_tf32<2>,  cudaFuncAttributeMaxDynamicSharedMemorySize, TF32_SMEM_BYTES);
        cudaFuncSetAttribute(gemm_tf32_dual, cudaFuncAttributeMaxDynamicSharedMemorySize, TF32_SMEM_BYTES);
        attr_done = true;
    }

    // degree counts
    cudaMemsetAsync(pCnt, 0, NN * sizeof(int));
    count_edges<<<EE / 256, 256>>>(dstI);
    calc_inv<<<NN / 256, 256>>>();

    // ---- layer 1 ----
    {
        dim3 gl(128 / 64, NN / 128);
        sgemm_nt<0><<<gl, 256>>>(x, W1l, nullptr, pP,   NN, 128, 128);
        sgemm_nt<0><<<gl, 256>>>(x, W1r, b1l,     pPre, NN, 128, 128);
        cudaMemsetAsync(pAgg, 0, (size_t)NN * 128 * sizeof(float));
        scatter_add<128><<<EE * 32 / 256, 256>>>(srcI, dstI, pP);
        cudaMemsetAsync(pStat, 0, 256 * sizeof(float));
        combine_stats<128><<<NN / 128, 256>>>(pPre);
        finalize_stats<128><<<1, 128>>>(gm1, be1);
        bn_relu_kernel<128><<<NN * 128 / 4 / 256, 256>>>(pPre, pA);
    }
    // ---- layer 2 ----
    {
        dim3 gl(128 / 64, NN / 128);
        sgemm_nt<0><<<gl, 256>>>(pA, W2l, nullptr, pP,   NN, 128, 128);
        sgemm_nt<0><<<gl, 256>>>(pA, W2r, b2l,     pPre, NN, 128, 128);
        cudaMemsetAsync(pAgg, 0, (size_t)NN * 128 * sizeof(float));
        scatter_add<128><<<EE * 32 / 256, 256>>>(srcI, dstI, pP);
        cudaMemsetAsync(pStat, 0, 256 * sizeof(float));
        combine_stats<128><<<NN / 128, 256>>>(pPre);
        finalize_stats<128><<<1, 128>>>(gm2, be2);
        bn_relu_kernel<128><<<NN * 128 / 4 / 256, 256>>>(pPre, pB);
    }
    // ---- layer 3 (H=64) ----
    {
        dim3 gl(64 / 64, NN / 128);
        sgemm_nt<0><<<gl, 256>>>(pB, W3l, nullptr, pP,   NN, 64, 128);
        sgemm_nt<0><<<gl, 256>>>(pB, W3r, b3l,     pPre, NN, 64, 128);
        cudaMemsetAsync(pAgg, 0, (size_t)NN * 64 * sizeof(float));
        scatter_add<64><<<EE * 16 / 256, 256>>>(srcI, dstI, pP);
        cudaMemsetAsync(pStat, 0, 256 * sizeof(float));
        combine_stats<64><<<NN / 128, 256>>>(pPre);
        finalize_stats<64><<<1, 64>>>(gm3, be3);
        bn_relu_kernel<64><<<NN * 64 / 4 / 256, 256>>>(pPre, pA);
    }

    // ---- head: bufA viewed as [256, 16384], tensor-core tf32 ----
    {
        gemm_tf32<2><<<dim3(LIN_OUTX / 64, 1), 256, TF32_SMEM_BYTES>>>(
            pA, Wlin, blin, pY1, LIN_OUTX, LIN_INX);
        gemm_tf32_dual<<<dim3(2 * LIN_OUTX / 64, 1), 256, TF32_SMEM_BYTES>>>(
            pY1, Wmu, bmu, pMu, Wsig, bsig, pSg, LIN_OUTX, LIN_OUTX);
        head_bn<<<(LIN_OUTX + 255) / 256, 256>>>(pMu, gfx, bfx, out);
        head_bn<<<(LIN_OUTX + 255) / 256, 256>>>(pSg, gfs, bfs, out + (size_t)BB * LIN_OUTX);
    }
}

// round 3
// speedup vs baseline: 2.2373x; 1.9337x over previous
#include <cuda_runtime.h>
#include <cuda_fp16.h>
#include <math.h>
#include <stdint.h>

// ---------------- problem constants ----------------
#define NN      65536      // nodes
#define EE      1048576    // edges
#define BB      256        // graphs
#define LIN_INX 16384
#define LIN_OUTX 6400
#define EPSBN   1e-5f

// ---------------- scratch (device globals; allocation-free) ----------------
__device__ __align__(16) float g_P  [NN * 128];   // x @ Wl^T  (scatter source)
__device__ __align__(16) float g_pre[NN * 128];   // x @ Wr^T + b, then += agg*inv
__device__ __align__(16) float g_agg[NN * 128];   // scatter destination
__device__ __align__(16) float g_bufA[NN * 128];  // layer outputs (ping)
__device__ __align__(16) float g_bufB[NN * 128];  // layer outputs (pong)
__device__ __align__(16) float g_Y1 [BB * LIN_OUTX];
__device__ __align__(16) float g_mu [BB * LIN_OUTX];
__device__ __align__(16) float g_sg [BB * LIN_OUTX];
__device__ float g_inv[NN];
__device__ int   g_cnt[NN];
__device__ float g_stats[256];   // [0:128) sum, [128:256) sumsq
__device__ float g_scale[128];
__device__ float g_shift[128];

// ---------------- small kernels ----------------
__global__ void count_edges(const int* __restrict__ dst) {
    int e = blockIdx.x * blockDim.x + threadIdx.x;
    if (e < EE) atomicAdd(&g_cnt[__ldg(dst + e)], 1);
}

__global__ void calc_inv() {
    int i = blockIdx.x * blockDim.x + threadIdx.x;
    if (i < NN) g_inv[i] = 1.0f / fmaxf((float)g_cnt[i], 1.0f);
}

// scatter: agg[dst] += P[src], vector f32x4 reductions (sm_90+)
template<int H>
__global__ void scatter_add(const int* __restrict__ src, const int* __restrict__ dst,
                            const float* __restrict__ P) {
    const int H4 = H / 4;
    unsigned idx = blockIdx.x * blockDim.x + threadIdx.x;   // total = EE*H4 (exact)
    int e = idx / H4;
    int s = idx - e * H4;
    int sn = __ldg(src + e);
    int dn = __ldg(dst + e);
    float4 v = *(const float4*)(P + (size_t)sn * H + s * 4);
    float* a = g_agg + (size_t)dn * H + s * 4;
    asm volatile("red.global.add.v4.f32 [%0], {%1,%2,%3,%4};"
                 :: "l"(a), "f"(v.x), "f"(v.y), "f"(v.z), "f"(v.w) : "memory");
}

// pre += agg*inv (in place) and accumulate per-column sum/sumsq
template<int H>
__global__ void __launch_bounds__(256) combine_stats(float* __restrict__ pre) {
    const int G = 256 / H;
    const int ROWS = 128;
    int tid = threadIdx.x;
    int col = tid % H;
    int rg  = tid / H;
    size_t base = (size_t)blockIdx.x * ROWS;
    float s = 0.f, s2 = 0.f;
    for (int r = rg; r < ROWS; r += G) {
        size_t i = base + r;
        float v = pre[i * H + col] + g_agg[i * H + col] * g_inv[i];
        pre[i * H + col] = v;
        s += v; s2 += v * v;
    }
    __shared__ float sh[256], sh2[256];
    sh[tid] = s; sh2[tid] = s2;
    __syncthreads();
    if (rg == 0) {
#pragma unroll
        for (int g = 1; g < G; g++) { s += sh[g * H + col]; s2 += sh2[g * H + col]; }
        atomicAdd(&g_stats[col], s);
        atomicAdd(&g_stats[128 + col], s2);
    }
}

template<int H>
__global__ void finalize_stats(const float* __restrict__ gamma, const float* __restrict__ beta) {
    int c = threadIdx.x;
    if (c < H) {
        float m   = g_stats[c] * (1.0f / NN);
        float var = g_stats[128 + c] * (1.0f / NN) - m * m;
        float sc  = gamma[c] * rsqrtf(var + EPSBN);
        g_scale[c] = sc;
        g_shift[c] = beta[c] - m * sc;
    }
}

template<int H>
__global__ void bn_relu_kernel(const float* __restrict__ pre, float* __restrict__ out) {
    unsigned idx = blockIdx.x * blockDim.x + threadIdx.x;   // total = NN*H/4 (exact)
    float4 v = *(const float4*)(pre + (size_t)idx * 4);
    int c = (idx * 4) & (H - 1);
    v.x = fmaxf(fmaf(v.x, g_scale[c + 0], g_shift[c + 0]), 0.f);
    v.y = fmaxf(fmaf(v.y, g_scale[c + 1], g_shift[c + 1]), 0.f);
    v.z = fmaxf(fmaf(v.z, g_scale[c + 2], g_shift[c + 2]), 0.f);
    v.w = fmaxf(fmaf(v.w, g_scale[c + 3], g_shift[c + 3]), 0.f);
    *(float4*)(out + (size_t)idx * 4) = v;
}

// final head batchnorm over 256 rows, one thread per column
__global__ void head_bn(const float* __restrict__ P, const float* __restrict__ gamma,
                        const float* __restrict__ beta, float* __restrict__ out) {
    int c = blockIdx.x * blockDim.x + threadIdx.x;
    if (c >= LIN_OUTX) return;
    float s = 0.f, s2 = 0.f;
    for (int r = 0; r < BB; r++) {
        float v = P[(size_t)r * LIN_OUTX + c];
        s += v; s2 += v * v;
    }
    float m   = s * (1.0f / BB);
    float var = s2 * (1.0f / BB) - m * m;
    float sc  = gamma[c] * rsqrtf(var + EPSBN);
    float shf = beta[c] - m * sc;
    for (int r = 0; r < BB; r++)
        out[(size_t)r * LIN_OUTX + c] = P[(size_t)r * LIN_OUTX + c] * sc + shf;
}

// ---------------- fp32 SGEMM (layer GEMMs, K=128) ----------------
template<int ACT>
__global__ void __launch_bounds__(256) sgemm_nt(
    const float* __restrict__ A, const float* __restrict__ W,
    const float* __restrict__ bias, float* __restrict__ C,
    int M, int N, int K)
{
    __shared__ float As[16][132];
    __shared__ float Ws[16][68];
    const int tid = threadIdx.x;
    const int m0 = blockIdx.y * 128;
    const int n0 = blockIdx.x * 64;
    const int tx = tid & 15;
    const int ty = tid >> 4;
    const int lr = tid >> 2;       // 0..63
    const int lq = (tid & 3) * 4;  // 0,4,8,12

    const float* Ag0 = A + (size_t)(m0 + lr) * K + lq;
    const float* Ag1 = A + (size_t)(m0 + 64 + lr) * K + lq;
    const float* Wg  = W + (size_t)(n0 + lr) * K + lq;

    float acc[8][4];
#pragma unroll
    for (int i = 0; i < 8; i++)
#pragma unroll
        for (int j = 0; j < 4; j++) acc[i][j] = 0.f;

    float4 a0 = *(const float4*)(Ag0);
    float4 a1 = *(const float4*)(Ag1);
    float4 w0 = *(const float4*)(Wg);

    for (int kt = 0; kt < K; kt += 16) {
        __syncthreads();
        As[lq + 0][lr]      = a0.x; As[lq + 1][lr]      = a0.y;
        As[lq + 2][lr]      = a0.z; As[lq + 3][lr]      = a0.w;
        As[lq + 0][lr + 64] = a1.x; As[lq + 1][lr + 64] = a1.y;
        As[lq + 2][lr + 64] = a1.z; As[lq + 3][lr + 64] = a1.w;
        Ws[lq + 0][lr] = w0.x; Ws[lq + 1][lr] = w0.y;
        Ws[lq + 2][lr] = w0.z; Ws[lq + 3][lr] = w0.w;
        __syncthreads();

        int kn = kt + 16;
        if (kn < K) {
            a0 = *(const float4*)(Ag0 + kn);
            a1 = *(const float4*)(Ag1 + kn);
            w0 = *(const float4*)(Wg  + kn);
        }

#pragma unroll
        for (int k = 0; k < 16; k++) {
            float4 aa0 = *(const float4*)&As[k][ty * 8];
            float4 aa1 = *(const float4*)&As[k][ty * 8 + 4];
            float4 bb  = *(const float4*)&Ws[k][tx * 4];
            float a[8] = {aa0.x, aa0.y, aa0.z, aa0.w, aa1.x, aa1.y, aa1.z, aa1.w};
            float b[4] = {bb.x, bb.y, bb.z, bb.w};
#pragma unroll
            for (int i = 0; i < 8; i++)
#pragma unroll
                for (int j = 0; j < 4; j++)
                    acc[i][j] = fmaf(a[i], b[j], acc[i][j]);
        }
    }

    float4 bv = make_float4(0.f, 0.f, 0.f, 0.f);
    if (bias) bv = *(const float4*)(bias + n0 + tx * 4);
#pragma unroll
    for (int i = 0; i < 8; i++) {
        float4 o;
        o.x = acc[i][0] + bv.x; o.y = acc[i][1] + bv.y;
        o.z = acc[i][2] + bv.z; o.w = acc[i][3] + bv.w;
        if (ACT == 2) { o.x = tanhf(o.x); o.y = tanhf(o.y); o.z = tanhf(o.z); o.w = tanhf(o.w); }
        *(float4*)(C + (size_t)(m0 + ty * 8 + i) * N + n0 + tx * 4) = o;
    }
}

// ---------------- fp16 tensor-core GEMM (head GEMMs) ----------------
// C[256, N] = act(A[256, K] @ W[N, K]^T + bias), fp32 in/out, fp16 mma, fp32 accum.
// BM=256 (whole M), BN=64, BK=32. 8 warps: 4 along M (64 rows) x 2 along N (32 cols).
// Double-buffered smem of half2 words; m16n8k16 fragment words match the
// word-addressing of the (verified) m16n8k8 tf32 layout.

__device__ __forceinline__ void mma_f16(float c[4], const uint32_t a[4], const uint32_t b[2]) {
    asm("mma.sync.aligned.m16n8k16.row.col.f32.f16.f16.f32 "
        "{%0,%1,%2,%3},{%4,%5,%6,%7},{%8,%9},{%0,%1,%2,%3};"
        : "+f"(c[0]), "+f"(c[1]), "+f"(c[2]), "+f"(c[3])
        : "r"(a[0]), "r"(a[1]), "r"(a[2]), "r"(a[3]), "r"(b[0]), "r"(b[1]));
}

#define TPITCH 20                      // 16 half2-words (BK=32 halves) + 4 pad
#define ABUF   (256 * TPITCH)          // 5120 words
#define WBASE  (2 * ABUF)              // 10240
#define WBUF   (64 * TPITCH)           // 1280
#define HGEMM_SMEM_BYTES ((WBASE + 2 * WBUF) * 4)   // 51200

__device__ __forceinline__ uint32_t pack_h2(float x, float y) {
    __half2 h = __float22half2_rn(make_float2(x, y));
    return *(uint32_t*)&h;
}

__device__ __forceinline__ void gemm_f16_core(
    const float* __restrict__ A, const float* __restrict__ W,
    const float* __restrict__ bias, float* __restrict__ C,
    int N, int K, int n0, int act, uint32_t* sh)
{
    const int tid  = threadIdx.x;
    const int lane = tid & 31;
    const int wid  = tid >> 5;
    const int mw   = wid & 3;          // 0..3  -> 64 M-rows each
    const int nw   = wid >> 2;         // 0..1  -> 32 N-cols each
    const int gid  = lane >> 2;        // 0..7
    const int tig  = lane & 3;         // 0..3

    const int arow = tid >> 2;         // 0..63 (load row within 64-row group)
    const int ac4  = tid & 3;          // which 4-float chunk of a 16-float half-tile

    const float* Ag = A + (size_t)arow * K + ac4 * 4;
    const float* Wg = W + (size_t)(n0 + arow) * K + ac4 * 4;

    float acc[4][4][4];
#pragma unroll
    for (int i = 0; i < 4; i++)
#pragma unroll
        for (int j = 0; j < 4; j++)
#pragma unroll
            for (int q = 0; q < 4; q++) acc[i][j][q] = 0.f;

    float4 av[4][2], wv[2];

    // prologue: load tile 0 (BK=32 floats per row -> 2 float4 per thread per row)
#pragma unroll
    for (int t = 0; t < 4; t++) {
        av[t][0] = *(const float4*)(Ag + (size_t)(64 * t) * K);
        av[t][1] = *(const float4*)(Ag + (size_t)(64 * t) * K + 16);
    }
    wv[0] = *(const float4*)(Wg);
    wv[1] = *(const float4*)(Wg + 16);

    auto store_tile = [&](int buf) {
        uint32_t* ap = sh + buf * ABUF;
        uint32_t* wp = sh + WBASE + buf * WBUF;
#pragma unroll
        for (int t = 0; t < 4; t++) {
            uint32_t* d = ap + (arow + 64 * t) * TPITCH;
            // words [0..7] = k 0..15, words [8..15] = k 16..31
            *(uint2*)(d + ac4 * 2)     = make_uint2(pack_h2(av[t][0].x, av[t][0].y),
                                                    pack_h2(av[t][0].z, av[t][0].w));
            *(uint2*)(d + 8 + ac4 * 2) = make_uint2(pack_h2(av[t][1].x, av[t][1].y),
                                                    pack_h2(av[t][1].z, av[t][1].w));
        }
        uint32_t* d = wp + arow * TPITCH;
        *(uint2*)(d + ac4 * 2)     = make_uint2(pack_h2(wv[0].x, wv[0].y),
                                                pack_h2(wv[0].z, wv[0].w));
        *(uint2*)(d + 8 + ac4 * 2) = make_uint2(pack_h2(wv[1].x, wv[1].y),
                                                pack_h2(wv[1].z, wv[1].w));
    };

    store_tile(0);
    __syncthreads();

    const int ntiles = K / 32;
    for (int it = 0; it < ntiles; it++) {
        int buf = it & 1;
        if (it + 1 < ntiles) {          // prefetch next tile into regs
            int kn = (it + 1) * 32;
#pragma unroll
            for (int t = 0; t < 4; t++) {
                av[t][0] = *(const float4*)(Ag + (size_t)(64 * t) * K + kn);
                av[t][1] = *(const float4*)(Ag + (size_t)(64 * t) * K + kn + 16);
            }
            wv[0] = *(const float4*)(Wg + kn);
            wv[1] = *(const float4*)(Wg + kn + 16);
        }

        const uint32_t* ap = sh + buf * ABUF;
        const uint32_t* wp = sh + WBASE + buf * WBUF;

#pragma unroll
        for (int s = 0; s < 2; s++) {          // two k16 steps per BK=32 tile
            const int k0 = s * 8;              // word offset
            uint32_t afr[4][4], bfr[4][2];
#pragma unroll
            for (int i = 0; i < 4; i++) {
                int r = mw * 64 + i * 16 + gid;
                afr[i][0] = ap[(r    ) * TPITCH + k0 + tig];
                afr[i][1] = ap[(r + 8) * TPITCH + k0 + tig];
                afr[i][2] = ap[(r    ) * TPITCH + k0 + tig + 4];
                afr[i][3] = ap[(r + 8) * TPITCH + k0 + tig + 4];
            }
#pragma unroll
            for (int j = 0; j < 4; j++) {
                int r = nw * 32 + j * 8 + gid;
                bfr[j][0] = wp[r * TPITCH + k0 + tig];
                bfr[j][1] = wp[r * TPITCH + k0 + tig + 4];
            }
#pragma unroll
            for (int i = 0; i < 4; i++)
#pragma unroll
                for (int j = 0; j < 4; j++)
                    mma_f16(acc[i][j], afr[i], bfr[j]);
        }

        if (it + 1 < ntiles) store_tile(buf ^ 1);
        __syncthreads();
    }

    // epilogue (same C-fragment layout as m16n8k8)
#pragma unroll
    for (int i = 0; i < 4; i++) {
        int mrow = mw * 64 + i * 16 + gid;
#pragma unroll
        for (int j = 0; j < 4; j++) {
            int ncol = n0 + nw * 32 + j * 8 + 2 * tig;
            float bx = bias ? bias[ncol] : 0.f;
            float by = bias ? bias[ncol + 1] : 0.f;
            float o0 = acc[i][j][0] + bx, o1 = acc[i][j][1] + by;
            float o2 = acc[i][j][2] + bx, o3 = acc[i][j][3] + by;
            if (act == 2) { o0 = tanhf(o0); o1 = tanhf(o1); o2 = tanhf(o2); o3 = tanhf(o3); }
            *(float2*)(C + (size_t)mrow * N + ncol)       = make_float2(o0, o1);
            *(float2*)(C + (size_t)(mrow + 8) * N + ncol) = make_float2(o2, o3);
        }
    }
}

template<int ACT>
__global__ void __launch_bounds__(256, 1) gemm_f16(
    const float* __restrict__ A, const float* __restrict__ W,
    const float* __restrict__ bias, float* __restrict__ C, int N, int K)
{
    extern __shared__ uint32_t sh[];
    gemm_f16_core(A, W, bias, C, N, K, blockIdx.x * 64, ACT, sh);
}

// fused mu+sigma: same A, two weight sets; grid.x = 2 * (N/64)
__global__ void __launch_bounds__(256, 1) gemm_f16_dual(
    const float* __restrict__ A,
    const float* __restrict__ W0, const float* __restrict__ b0, float* __restrict__ C0,
    const float* __restrict__ W1, const float* __restrict__ b1, float* __restrict__ C1,
    int N, int K)
{
    extern __shared__ uint32_t sh[];
    int nblk = N / 64;
    int bx = blockIdx.x;
    if (bx < nblk)
        gemm_f16_core(A, W0, b0, C0, N, K, bx * 64, 0, sh);
    else
        gemm_f16_core(A, W1, b1, C1, N, K, (bx - nblk) * 64, 0, sh);
}

// ---------------- host orchestration ----------------
static void* symaddr(const void* sym) {
    void* p = nullptr;
    cudaGetSymbolAddress(&p, sym);
    return p;
}

extern "C" void kernel_launch(void* const* d_in, const int* in_sizes, int n_in,
                              void* d_out, int out_size)
{
    const float* x    = (const float*)d_in[0];
    const int*   ei   = (const int*)  d_in[1];
    const int*   srcI = ei;
    const int*   dstI = ei + EE;
    const float *W1l = (const float*)d_in[3],  *b1l = (const float*)d_in[4],  *W1r = (const float*)d_in[5];
    const float *gm1 = (const float*)d_in[6],  *be1 = (const float*)d_in[7];
    const float *W2l = (const float*)d_in[8],  *b2l = (const float*)d_in[9],  *W2r = (const float*)d_in[10];
    const float *gm2 = (const float*)d_in[11], *be2 = (const float*)d_in[12];
    const float *W3l = (const float*)d_in[13], *b3l = (const float*)d_in[14], *W3r = (const float*)d_in[15];
    const float *gm3 = (const float*)d_in[16], *be3 = (const float*)d_in[17];
    const float *Wlin = (const float*)d_in[18], *blin = (const float*)d_in[19];
    const float *Wmu  = (const float*)d_in[20], *bmu  = (const float*)d_in[21];
    const float *Wsig = (const float*)d_in[22], *bsig = (const float*)d_in[23];
    const float *gfx  = (const float*)d_in[24], *bfx  = (const float*)d_in[25];
    const float *gfs  = (const float*)d_in[26], *bfs  = (const float*)d_in[27];
    float* out = (float*)d_out;

    float* pP    = (float*)symaddr(g_P);
    float* pPre  = (float*)symaddr(g_pre);
    float* pAgg  = (float*)symaddr(g_agg);
    float* pA    = (float*)symaddr(g_bufA);
    float* pB    = (float*)symaddr(g_bufB);
    float* pY1   = (float*)symaddr(g_Y1);
    float* pMu   = (float*)symaddr(g_mu);
    float* pSg   = (float*)symaddr(g_sg);
    int*   pCnt  = (int*)  symaddr(g_cnt);
    float* pStat = (float*)symaddr(g_stats);

    static bool attr_done = false;
    if (!attr_done) {
        cudaFuncSetAttribute(gemm_f16<0>,   cudaFuncAttributeMaxDynamicSharedMemorySize, HGEMM_SMEM_BYTES);
        cudaFuncSetAttribute(gemm_f16<2>,   cudaFuncAttributeMaxDynamicSharedMemorySize, HGEMM_SMEM_BYTES);
        cudaFuncSetAttribute(gemm_f16_dual, cudaFuncAttributeMaxDynamicSharedMemorySize, HGEMM_SMEM_BYTES);
        attr_done = true;
    }

    // degree counts
    cudaMemsetAsync(pCnt, 0, NN * sizeof(int));
    count_edges<<<EE / 256, 256>>>(dstI);
    calc_inv<<<NN / 256, 256>>>();

    // ---- layer 1 ----
    {
        dim3 gl(128 / 64, NN / 128);
        sgemm_nt<0><<<gl, 256>>>(x, W1l, nullptr, pP,   NN, 128, 128);
        sgemm_nt<0><<<gl, 256>>>(x, W1r, b1l,     pPre, NN, 128, 128);
        cudaMemsetAsync(pAgg, 0, (size_t)NN * 128 * sizeof(float));
        scatter_add<128><<<EE * 32 / 256, 256>>>(srcI, dstI, pP);
        cudaMemsetAsync(pStat, 0, 256 * sizeof(float));
        combine_stats<128><<<NN / 128, 256>>>(pPre);
        finalize_stats<128><<<1, 128>>>(gm1, be1);
        bn_relu_kernel<128><<<NN * 128 / 4 / 256, 256>>>(pPre, pA);
    }
    // ---- layer 2 ----
    {
        dim3 gl(128 / 64, NN / 128);
        sgemm_nt<0><<<gl, 256>>>(pA, W2l, nullptr, pP,   NN, 128, 128);
        sgemm_nt<0><<<gl, 256>>>(pA, W2r, b2l,     pPre, NN, 128, 128);
        cudaMemsetAsync(pAgg, 0, (size_t)NN * 128 * sizeof(float));
        scatter_add<128><<<EE * 32 / 256, 256>>>(srcI, dstI, pP);
        cudaMemsetAsync(pStat, 0, 256 * sizeof(float));
        combine_stats<128><<<NN / 128, 256>>>(pPre);
        finalize_stats<128><<<1, 128>>>(gm2, be2);
        bn_relu_kernel<128><<<NN * 128 / 4 / 256, 256>>>(pPre, pB);
    }
    // ---- layer 3 (H=64) ----
    {
        dim3 gl(64 / 64, NN / 128);
        sgemm_nt<0><<<gl, 256>>>(pB, W3l, nullptr, pP,   NN, 64, 128);
        sgemm_nt<0><<<gl, 256>>>(pB, W3r, b3l,     pPre, NN, 64, 128);
        cudaMemsetAsync(pAgg, 0, (size_t)NN * 64 * sizeof(float));
        scatter_add<64><<<EE * 16 / 256, 256>>>(srcI, dstI, pP);
        cudaMemsetAsync(pStat, 0, 256 * sizeof(float));
        combine_stats<64><<<NN / 128, 256>>>(pPre);
        finalize_stats<64><<<1, 64>>>(gm3, be3);
        bn_relu_kernel<64><<<NN * 64 / 4 / 256, 256>>>(pPre, pA);
    }

    // ---- head: bufA viewed as [256, 16384], fp16 tensor cores ----
    {
        gemm_f16<2><<<dim3(LIN_OUTX / 64, 1), 256, HGEMM_SMEM_BYTES>>>(
            pA, Wlin, blin, pY1, LIN_OUTX, LIN_INX);
        gemm_f16_dual<<<dim3(2 * LIN_OUTX / 64, 1), 256, HGEMM_SMEM_BYTES>>>(
            pY1, Wmu, bmu, pMu, Wsig, bsig, pSg, LIN_OUTX, LIN_OUTX);
        head_bn<<<(LIN_OUTX + 255) / 256, 256>>>(pMu, gfx, bfx, out);
        head_bn<<<(LIN_OUTX + 255) / 256, 256>>>(pSg, gfs, bfs, out + (size_t)BB * LIN_OUTX);
    }
}